// round 16
// baseline (speedup 1.0000x reference)
#include <cuda_runtime.h>
#include <math.h>

#define B_    128
#define TP2   2050
#define T_    2049
#define H_    64
#define G7    448    // 7*H real gates
#define K_    100
#define KE    103    // K+3 rows in in_emb
#define OPT   64     // out-proj threads (warps 0-1)
#define MVT   512    // matvec threads (warps 2-17): (j, y, z) k-split
#define NTHR  576    // 18 warps
#define PRE_W 256    // pretab entries per event (one per (j,y) pair)

// Packed input-projection table: pre2[e][j*4+y] = {pre(gate y*64+j), pre(gate (y+4)*64+j)}
__device__ float2 g_pretab2[KE * PRE_W];

__global__ void build_pretab(const float* __restrict__ in_emb,
                             const float* __restrict__ Wx,
                             const float* __restrict__ bias) {
    int e = blockIdx.x;
    int t = threadIdx.x;            // 0..255
    int j = t >> 2, y = t & 3;
    int glo = y * H_ + j;
    float lo = bias[glo];
#pragma unroll
    for (int k = 0; k < H_; ++k)
        lo = fmaf(in_emb[e * H_ + k], Wx[k * G7 + glo], lo);
    float hi = 0.f;
    if (y < 3) {
        int ghi = (y + 4) * H_ + j;
        hi = bias[ghi];
#pragma unroll
        for (int k = 0; k < H_; ++k)
            hi = fmaf(in_emb[e * H_ + k], Wx[k * G7 + ghi], hi);
    }
    g_pretab2[e * PRE_W + t] = make_float2(lo, hi);
}

// ---- packed f32x2 helpers ----
typedef unsigned long long u64;
__device__ __forceinline__ u64 pack2(float x, float y) {
    u64 r; asm("mov.b64 %0, {%1, %2};" : "=l"(r) : "f"(x), "f"(y)); return r;
}
__device__ __forceinline__ float2 unpack2(u64 v) {
    float2 r; asm("mov.b64 {%0, %1}, %2;" : "=f"(r.x), "=f"(r.y) : "l"(v)); return r;
}
__device__ __forceinline__ u64 ffma2_(u64 a, u64 b, u64 c) {
    u64 d; asm("fma.rn.f32x2 %0, %1, %2, %3;" : "=l"(d) : "l"(a), "l"(b), "l"(c));
    return d;
}
__device__ __forceinline__ u64 fadd2_(u64 a, u64 b) {
    u64 d; asm("add.rn.f32x2 %0, %1, %2;" : "=l"(d) : "l"(a), "l"(b));
    return d;
}

// ---- MUFU-based activations ----
__device__ __forceinline__ float tanh_ap(float x) {
    float y; asm("tanh.approx.f32 %0, %1;" : "=f"(y) : "f"(x)); return y;
}
__device__ __forceinline__ float ex2_(float x) {
    float y; asm("ex2.approx.f32 %0, %1;" : "=f"(y) : "f"(x)); return y;
}
__device__ __forceinline__ float lg2_(float x) {
    float y; asm("lg2.approx.f32 %0, %1;" : "=f"(y) : "f"(x)); return y;
}
__device__ __forceinline__ float fast_softplus(float x) {      // for outputs
    float e = __expf(-fabsf(x));
    return fmaxf(x, 0.f) + __logf(1.0f + e);
}
#define LOG2E 1.4426950408889634f

__global__ void __launch_bounds__(NTHR, 1)
scan_kernel(const int*   __restrict__ event_t,
            const float* __restrict__ dtime_t,
            const float* __restrict__ Wh,
            const float* __restrict__ out_emb,
            float*       __restrict__ out) {
    extern __shared__ float smem[];
    float2* pretab_s = (float2*)smem;                  // KE*PRE_W float2 (206 KB)
    float*  h_s      = smem + 2 * KE * PRE_W;          // 8*H floats (oct buffered)

    const int tid  = threadIdx.x;
    const int bb   = blockIdx.x;
    const int lane = tid & 31;

    const int*   ev_row  = event_t + bb * TP2;
    const float* dt_row  = dtime_t + bb * TP2;
    float*       out_row = out + (size_t)bb * T_ * K_;

    // ---- Stage packed PreTable into shared memory ----
    {
        const float4* src = (const float4*)g_pretab2;
        float4*       dst = (float4*)pretab_s;
        for (int i = tid; i < KE * PRE_W / 2; i += NTHR) dst[i] = src[i];
    }
    if (tid < H_) h_s[7 * H_ + tid] = 0.f;   // h_{-1} lives in buf7

    if (tid >= OPT) {
        // ===== matvec/update: warps 2-17, thread = (j, y, z) =====
        const int m = tid - OPT;             // 0..511
        const int z = m & 1;                 // k-half
        const int y = (m >> 1) & 3;          // gate-pair slot: gates y, y+4
        const int j = m >> 3;                // hidden unit 0..63
        const int base = lane & ~7;          // lane of (y=0,z=0) in this 8-lane group
        const int pidx = m >> 1;             // pretab pair index = j*4 + y

        // Register-resident Wh half-columns (32 k-values each)
        u64 wlo[16], whi[16];
        {
            const int glo = y * H_ + j;
            const int k0  = 32 * z;
#pragma unroll
            for (int k2 = 0; k2 < 16; ++k2)
                wlo[k2] = pack2(Wh[(k0 + 2 * k2) * G7 + glo],
                                Wh[(k0 + 2 * k2 + 1) * G7 + glo]);
            if (y < 3) {
                const int ghi = (y + 4) * H_ + j;
#pragma unroll
                for (int k2 = 0; k2 < 16; ++k2)
                    whi[k2] = pack2(Wh[(k0 + 2 * k2) * G7 + ghi],
                                    Wh[(k0 + 2 * k2 + 1) * G7 + ghi]);
            } else {
#pragma unroll
                for (int k2 = 0; k2 < 16; ++k2) whi[k2] = 0ull;
            }
        }

        float c = 0.f, cbv = 0.f;            // consistent across all 8 lanes
        // this lane's single activation:
        //   z==0: gate y   (y==2 -> tanh, else sigmoid)
        //   z==1: gate y+4 (y==2 -> exp(-delta*dt), else sigmoid)
        const bool tanh_lane  = (z == 0) && (y == 2);
        const bool delta_lane = (z == 1) && (y == 2);
        const float s0 = tanh_lane ? 1.0f : 0.5f;
        const float s1 = tanh_lane ? 1.0f : 0.5f;
        const float s2 = tanh_lane ? 0.0f : 0.5f;

        __syncthreads();                     // pretab + h_{-1} staged

        int   ev  = ev_row[0];
        float dtv = dt_row[1];
        float2 pre = pretab_s[ev * PRE_W + pidx];   // prefetched for t=0

#define MV_STEP(T_IDX)                                                         \
        {                                                                      \
            const int   t_ = (T_IDX);                                          \
            const float* hr = h_s + (((t_ + 7) & 7) * H_) + 32 * z;            \
            float*       hw = h_s + ((t_ & 7) * H_);                           \
            const int   ev_next = ev_row[t_ + 1];                              \
            const float dt_next = dt_row[(t_ + 2 < TP2) ? (t_ + 2) : (TP2 - 1)]; \
            const ulonglong2* h2 = (const ulonglong2*)hr;                      \
            u64 aL0 = pack2(z ? 0.f : pre.x, 0.f), aL1 = 0ull;                 \
            u64 aH0 = pack2(z ? 0.f : pre.y, 0.f), aH1 = 0ull;                 \
            u64 aL2 = 0ull, aL3 = 0ull, aH2 = 0ull, aH3 = 0ull;                \
            _Pragma("unroll")                                                  \
            for (int k4 = 0; k4 < 8; k4 += 2) {                                \
                ulonglong2 hp = h2[k4];                                        \
                aH0 = ffma2_(hp.x, whi[2 * k4],     aH0);                      \
                aH1 = ffma2_(hp.y, whi[2 * k4 + 1], aH1);                      \
                aL0 = ffma2_(hp.x, wlo[2 * k4],     aL0);                      \
                aL1 = ffma2_(hp.y, wlo[2 * k4 + 1], aL1);                      \
                ulonglong2 hq = h2[k4 + 1];                                    \
                aH2 = ffma2_(hq.x, whi[2 * k4 + 2], aH2);                      \
                aH3 = ffma2_(hq.y, whi[2 * k4 + 3], aH3);                      \
                aL2 = ffma2_(hq.x, wlo[2 * k4 + 2], aL2);                      \
                aL3 = ffma2_(hq.y, wlo[2 * k4 + 3], aL3);                      \
            }                                                                  \
            float2 rH = unpack2(fadd2_(fadd2_(aH0, aH1), fadd2_(aH2, aH3)));   \
            float2 rL = unpack2(fadd2_(fadd2_(aL0, aL1), fadd2_(aL2, aL3)));   \
            float gHp = rH.x + rH.y;                                           \
            float gLp = rL.x + rL.y;                                           \
            const float gHi = gHp + __shfl_xor_sync(0xffffffffu, gHp, 1);      \
            const float gLo = gLp + __shfl_xor_sync(0xffffffffu, gLp, 1);      \
            const float gsel = z ? gHi : gLo;                                  \
            float a = fmaf(s1, tanh_ap(s0 * gsel), s2);                        \
            if (delta_lane) a = ex2_(-dtv * lg2_(1.0f + ex2_(gHi * LOG2E)));   \
            pre = pretab_s[ev_next * PRE_W + pidx];                            \
            const float iv  = __shfl_sync(0xffffffffu, a, base + 0);           \
            const float ibv = __shfl_sync(0xffffffffu, a, base + 1);           \
            const float fv  = __shfl_sync(0xffffffffu, a, base + 2);           \
            const float fbv = __shfl_sync(0xffffffffu, a, base + 3);           \
            const float zv  = __shfl_sync(0xffffffffu, a, base + 4);           \
            const float ev_ = __shfl_sync(0xffffffffu, a, base + 5);           \
            const float ov  = __shfl_sync(0xffffffffu, a, base + 6);           \
            const float ci  = fmaf(fv, c, iv * zv);                            \
            const float cbi = fmaf(fbv, cbv, ibv * zv);                        \
            const float cn  = fmaf(ci - cbi, ev_, cbi);                        \
            c   = cn;                                                          \
            cbv = cbi;                                                         \
            const float hn = ov * tanh_ap(cn);                                 \
            if ((m & 7) == 0) hw[j] = hn;                                      \
            ev  = ev_next;                                                     \
            dtv = dt_next;                                                     \
        }

        // steps 0..2047 in 4-step phases: full sync at t%4==3, MV-only otherwise
        for (int t = 0; t < T_ - 1; ++t) {
            MV_STEP(t);
            if ((t & 3) == 3) {
                __syncthreads();
            } else {
                asm volatile("bar.sync 1, %0;" :: "r"(MVT) : "memory");
            }
        }
        MV_STEP(T_ - 1);                     // final step t = 2048 (buf 0)
        __syncthreads();                     // publish h_{T-1} to OP
#undef MV_STEP
    } else {
        // ===== out-proj: warps 0-1, four h vectors per phase =====
        const int ot = tid;                  // 0..63, active < 50
        const bool on = (ot < 50);
        const int k0 = 2 * ot, k1 = 2 * ot + 1;
        u64 oe0[H_ / 2], oe1[H_ / 2];
        if (on) {
#pragma unroll
            for (int i = 0; i < H_ / 2; ++i) {
                oe0[i] = pack2(out_emb[k0 * H_ + 2 * i], out_emb[k0 * H_ + 2 * i + 1]);
                oe1[i] = pack2(out_emb[k1 * H_ + 2 * i], out_emb[k1 * H_ + 2 * i + 1]);
            }
        } else {
#pragma unroll
            for (int i = 0; i < H_ / 2; ++i) { oe0[i] = 0ull; oe1[i] = 0ull; }
        }

        __syncthreads();                     // pretab + h_{-1} staged

        for (int p = 0; p < (T_ - 1) / 4; ++p) {
            __syncthreads();                 // end of MV phase p
#pragma unroll
            for (int q = 0; q < 4; ++q) {
                const int u = 4 * p + q;
                const ulonglong2* hp2 = (const ulonglong2*)(h_s + ((u & 7) * H_));
                u64 s00 = 0ull, s01 = 0ull, s10 = 0ull, s11 = 0ull;
#pragma unroll
                for (int i = 0; i < 16; ++i) {
                    ulonglong2 hv = hp2[i];
                    s00 = ffma2_(hv.x, oe0[2 * i],     s00);
                    s01 = ffma2_(hv.y, oe0[2 * i + 1], s01);
                    s10 = ffma2_(hv.x, oe1[2 * i],     s10);
                    s11 = ffma2_(hv.y, oe1[2 * i + 1], s11);
                }
                float2 r0 = unpack2(fadd2_(s00, s01));
                float2 r1 = unpack2(fadd2_(s10, s11));
                if (on) {
                    float* orow = out_row + (size_t)u * K_;
                    orow[k0] = fast_softplus(r0.x + r0.y);
                    orow[k1] = fast_softplus(r1.x + r1.y);
                }
            }
        }
        __syncthreads();                     // final MV step done
        // drain: u = T_-1 = 2048 (buf 0)
        {
            const ulonglong2* hp2 = (const ulonglong2*)(h_s + (((T_ - 1) & 7) * H_));
            u64 s00 = 0ull, s01 = 0ull, s10 = 0ull, s11 = 0ull;
#pragma unroll
            for (int i = 0; i < 16; ++i) {
                ulonglong2 hv = hp2[i];
                s00 = ffma2_(hv.x, oe0[2 * i],     s00);
                s01 = ffma2_(hv.y, oe0[2 * i + 1], s01);
                s10 = ffma2_(hv.x, oe1[2 * i],     s10);
                s11 = ffma2_(hv.y, oe1[2 * i + 1], s11);
            }
            float2 r0 = unpack2(fadd2_(s00, s01));
            float2 r1 = unpack2(fadd2_(s10, s11));
            if (on) {
                float* orow = out_row + (size_t)(T_ - 1) * K_;
                orow[k0] = fast_softplus(r0.x + r0.y);
                orow[k1] = fast_softplus(r1.x + r1.y);
            }
        }
    }
}

extern "C" void kernel_launch(void* const* d_in, const int* in_sizes, int n_in,
                              void* d_out, int out_size) {
    const int*   ev   = (const int*)  d_in[0];
    const float* dt   = (const float*)d_in[1];
    const float* iemb = (const float*)d_in[2];
    const float* Wx   = (const float*)d_in[3];
    const float* Wh   = (const float*)d_in[4];
    const float* bias = (const float*)d_in[5];
    const float* oemb = (const float*)d_in[6];
    float* out = (float*)d_out;

    const size_t smem_bytes = (size_t)(2 * KE * PRE_W + 8 * H_ + 16) * sizeof(float);
    cudaFuncSetAttribute(scan_kernel, cudaFuncAttributeMaxDynamicSharedMemorySize,
                         (int)smem_bytes);

    build_pretab<<<KE, PRE_W>>>(iemb, Wx, bias);
    scan_kernel<<<B_, NTHR, smem_bytes>>>(ev, dt, Wh, oemb, out);
}

// round 17
// speedup vs baseline: 4.2194x; 4.2194x over previous
#include <cuda_runtime.h>
#include <math.h>

#define B_    128
#define TP2   2050
#define T_    2049
#define H_    64
#define G7    448     // 7*H real gates
#define K_    100
#define KE    103     // K+3 rows in in_emb
#define OPT   64      // out-proj threads (warps 0-1)
#define MVT   256     // matvec threads (warps 2-9)
#define NTHR  320     // 10 warps

// Packed input-projection table: pre2[e][m] = {pre(gate y*64+j), pre(gate (y+4)*64+j)}
__device__ float2 g_pretab2[KE * MVT];

__global__ void build_pretab(const float* __restrict__ in_emb,
                             const float* __restrict__ Wx,
                             const float* __restrict__ bias) {
    int e = blockIdx.x;
    int t = threadIdx.x;            // 0..255
    int j = t >> 2, y = t & 3;
    int glo = y * H_ + j;
    float lo = bias[glo];
#pragma unroll
    for (int k = 0; k < H_; ++k)
        lo = fmaf(in_emb[e * H_ + k], Wx[k * G7 + glo], lo);
    float hi = 0.f;
    if (y < 3) {
        int ghi = (y + 4) * H_ + j;
        hi = bias[ghi];
#pragma unroll
        for (int k = 0; k < H_; ++k)
            hi = fmaf(in_emb[e * H_ + k], Wx[k * G7 + ghi], hi);
    }
    g_pretab2[e * MVT + t] = make_float2(lo, hi);
}

// ---- packed f32x2 helpers ----
typedef unsigned long long u64;
__device__ __forceinline__ u64 pack2(float x, float y) {
    u64 r; asm("mov.b64 %0, {%1, %2};" : "=l"(r) : "f"(x), "f"(y)); return r;
}
__device__ __forceinline__ float2 unpack2(u64 v) {
    float2 r; asm("mov.b64 {%0, %1}, %2;" : "=f"(r.x), "=f"(r.y) : "l"(v)); return r;
}
__device__ __forceinline__ u64 ffma2_(u64 a, u64 b, u64 c) {
    u64 d; asm("fma.rn.f32x2 %0, %1, %2, %3;" : "=l"(d) : "l"(a), "l"(b), "l"(c));
    return d;
}
__device__ __forceinline__ u64 fadd2_(u64 a, u64 b) {
    u64 d; asm("add.rn.f32x2 %0, %1, %2;" : "=l"(d) : "l"(a), "l"(b));
    return d;
}

// ---- MUFU-based activations ----
__device__ __forceinline__ float tanh_ap(float x) {
    float y; asm("tanh.approx.f32 %0, %1;" : "=f"(y) : "f"(x)); return y;
}
__device__ __forceinline__ float ex2_(float x) {
    float y; asm("ex2.approx.f32 %0, %1;" : "=f"(y) : "f"(x)); return y;
}
__device__ __forceinline__ float lg2_(float x) {
    float y; asm("lg2.approx.f32 %0, %1;" : "=f"(y) : "f"(x)); return y;
}
__device__ __forceinline__ float fast_softplus(float x) {      // for outputs
    float e = __expf(-fabsf(x));
    return fmaxf(x, 0.f) + __logf(1.0f + e);
}
#define LOG2E 1.4426950408889634f

__global__ void __launch_bounds__(NTHR, 1)
scan_kernel(const int*   __restrict__ event_t,
            const float* __restrict__ dtime_t,
            const float* __restrict__ Wh,
            const float* __restrict__ out_emb,
            float*       __restrict__ out) {
    extern __shared__ float smem[];
    float2* pretab_s = (float2*)smem;                  // KE*MVT float2 (206 KB)
    float*  h_s      = smem + 2 * KE * MVT;            // 8*H floats (oct buffered)

    const int tid  = threadIdx.x;
    const int bb   = blockIdx.x;
    const int lane = tid & 31;

    const int*   ev_row  = event_t + bb * TP2;
    const float* dt_row  = dtime_t + bb * TP2;
    float*       out_row = out + (size_t)bb * T_ * K_;

    // ---- Stage packed PreTable into shared memory ----
    {
        const float4* src = (const float4*)g_pretab2;
        float4*       dst = (float4*)pretab_s;
        for (int i = tid; i < KE * MVT / 2; i += NTHR) dst[i] = src[i];
    }
    if (tid < H_) h_s[7 * H_ + tid] = 0.f;   // h_{-1} lives in buf7

    if (tid >= OPT) {
        // ===== matvec/update: warps 2-9 =====
        const int m = tid - OPT;             // 0..255
        const int y = m & 3;                 // gates y and y+4
        const int j = m >> 2;                // hidden unit 0..63
        const int base = lane & ~3;          // lane of y==0 in this 4-lane group

        // Register-resident Wh columns for gates glo = y*64+j, ghi = (y+4)*64+j
        u64 wlo[H_ / 2], whi[H_ / 2];
        {
            const int glo = y * H_ + j;
#pragma unroll
            for (int k2 = 0; k2 < H_ / 2; ++k2)
                wlo[k2] = pack2(Wh[(2 * k2) * G7 + glo], Wh[(2 * k2 + 1) * G7 + glo]);
            if (y < 3) {
                const int ghi = (y + 4) * H_ + j;
#pragma unroll
                for (int k2 = 0; k2 < H_ / 2; ++k2)
                    whi[k2] = pack2(Wh[(2 * k2) * G7 + ghi], Wh[(2 * k2 + 1) * G7 + ghi]);
            } else {
#pragma unroll
                for (int k2 = 0; k2 < H_ / 2; ++k2) whi[k2] = 0ull;
            }
        }

        float c = 0.f, cbv = 0.f;            // valid in y==0 lanes
        const float s0 = (y == 2) ? 1.0f : 0.5f;
        const float s1 = (y == 2) ? 1.0f : 0.5f;
        const float s2 = (y == 2) ? 0.0f : 0.5f;
        const bool  is_delta = (y == 2);     // hi gate of y==2 is the delta gate

        __syncthreads();                     // pretab + h_{-1} staged

        int   ev  = ev_row[0];
        float dtv = dt_row[1];
        float2 pre = pretab_s[ev * MVT + m]; // prefetched for t=0

        // one LSTM step; writes h_t into buf t&7, reads h_{t-1} from buf (t+7)&7
#define MV_STEP(T_IDX)                                                         \
        {                                                                      \
            const int   t_ = (T_IDX);                                          \
            const float* hr = h_s + (((t_ + 7) & 7) * H_);                     \
            float*       hw = h_s + ((t_ & 7) * H_);                           \
            const int   ev_next = ev_row[t_ + 1];                              \
            const float dt_next = dt_row[(t_ + 2 < TP2) ? (t_ + 2) : (TP2 - 1)]; \
            const ulonglong2* h2 = (const ulonglong2*)hr;                      \
            u64 aL0 = pack2(pre.x, 0.f), aL1 = 0ull, aL2 = 0ull, aL3 = 0ull;   \
            u64 aH0 = pack2(pre.y, 0.f), aH1 = 0ull, aH2 = 0ull, aH3 = 0ull;   \
            _Pragma("unroll")                                                  \
            for (int k4 = 0; k4 < 16; k4 += 2) {                               \
                ulonglong2 hp = h2[k4];                                        \
                aH0 = ffma2_(hp.x, whi[2 * k4],     aH0);                      \
                aH1 = ffma2_(hp.y, whi[2 * k4 + 1], aH1);                      \
                aL0 = ffma2_(hp.x, wlo[2 * k4],     aL0);                      \
                aL1 = ffma2_(hp.y, wlo[2 * k4 + 1], aL1);                      \
                ulonglong2 hq = h2[k4 + 1];                                    \
                aH2 = ffma2_(hq.x, whi[2 * k4 + 2], aH2);                      \
                aH3 = ffma2_(hq.y, whi[2 * k4 + 3], aH3);                      \
                aL2 = ffma2_(hq.x, wlo[2 * k4 + 2], aL2);                      \
                aL3 = ffma2_(hq.y, wlo[2 * k4 + 3], aL3);                      \
            }                                                                  \
            float2 rH = unpack2(fadd2_(fadd2_(aH0, aH1), fadd2_(aH2, aH3)));   \
            const float gHi = rH.x + rH.y;                                     \
            /* branch-free: compute both arms, SEL on per-thread constant */   \
            const float dHi = ex2_(-dtv * lg2_(1.0f + ex2_(gHi * LOG2E)));     \
            const float sHi = fmaf(0.5f, tanh_ap(0.5f * gHi), 0.5f);           \
            const float aHi = is_delta ? dHi : sHi;                            \
            float2 rL = unpack2(fadd2_(fadd2_(aL0, aL1), fadd2_(aL2, aL3)));   \
            const float gLo = rL.x + rL.y;                                     \
            const float aLo = fmaf(s1, tanh_ap(s0 * gLo), s2);                 \
            pre = pretab_s[ev_next * MVT + m];                                 \
            const float fbv = __shfl_sync(0xffffffffu, aHi, base + 1);         \
            const float ev_ = __shfl_sync(0xffffffffu, aHi, base + 2);         \
            const float fv  = __shfl_sync(0xffffffffu, aLo, base + 1);         \
            const float zv  = __shfl_sync(0xffffffffu, aLo, base + 2);         \
            const float ov  = __shfl_sync(0xffffffffu, aLo, base + 3);         \
            const float ci  = fmaf(fv, c, aLo * zv);                           \
            const float cbi = fmaf(fbv, cbv, aHi * zv);                        \
            const float cn  = fmaf(ci - cbi, ev_, cbi);                        \
            c   = cn;                                                          \
            cbv = cbi;                                                         \
            const float hn = ov * tanh_ap(cn);                                 \
            if (y == 0) hw[j] = hn;                                            \
            ev  = ev_next;                                                     \
            dtv = dt_next;                                                     \
        }
#define MV_BAR() asm volatile("bar.sync 1, %0;" :: "r"(MVT) : "memory")

        // steps 0..2047 in straight-line 4-step groups (2048 = 4*512):
        // MV-only barrier between steps, full barrier closing each group
        for (int t = 0; t < T_ - 1; t += 4) {
            MV_STEP(t);     MV_BAR();
            MV_STEP(t + 1); MV_BAR();
            MV_STEP(t + 2); MV_BAR();
            MV_STEP(t + 3); __syncthreads();
        }
        // final step t = 2048 (writes buf 0; OP finished reading step-2040 buf0
        // at the t=2047 full sync)
        MV_STEP(T_ - 1);
        __syncthreads();                     // publish h_{T-1} to OP
#undef MV_STEP
#undef MV_BAR
    } else {
        // ===== out-proj: warps 0-1, four h vectors per phase =====
        const int ot = tid;                  // 0..63, active < 50
        const bool on = (ot < 50);
        const int k0 = 2 * ot, k1 = 2 * ot + 1;
        u64 oe0[H_ / 2], oe1[H_ / 2];
        if (on) {
#pragma unroll
            for (int i = 0; i < H_ / 2; ++i) {
                oe0[i] = pack2(out_emb[k0 * H_ + 2 * i], out_emb[k0 * H_ + 2 * i + 1]);
                oe1[i] = pack2(out_emb[k1 * H_ + 2 * i], out_emb[k1 * H_ + 2 * i + 1]);
            }
        } else {
#pragma unroll
            for (int i = 0; i < H_ / 2; ++i) { oe0[i] = 0ull; oe1[i] = 0ull; }
        }

        __syncthreads();                     // pretab + h_{-1} staged

        // phase p (p=0..511): after sync, h_{4p}..h_{4p+3} are ready
        for (int p = 0; p < (T_ - 1) / 4; ++p) {
            __syncthreads();                 // end of MV phase p
#pragma unroll
            for (int q = 0; q < 4; ++q) {
                const int u = 4 * p + q;
                const ulonglong2* hp2 = (const ulonglong2*)(h_s + ((u & 7) * H_));
                u64 s00 = 0ull, s01 = 0ull, s10 = 0ull, s11 = 0ull;
#pragma unroll
                for (int i = 0; i < 16; ++i) {
                    ulonglong2 hv = hp2[i];
                    s00 = ffma2_(hv.x, oe0[2 * i],     s00);
                    s01 = ffma2_(hv.y, oe0[2 * i + 1], s01);
                    s10 = ffma2_(hv.x, oe1[2 * i],     s10);
                    s11 = ffma2_(hv.y, oe1[2 * i + 1], s11);
                }
                float2 r0 = unpack2(fadd2_(s00, s01));
                float2 r1 = unpack2(fadd2_(s10, s11));
                if (on) {
                    float* orow = out_row + (size_t)u * K_;
                    orow[k0] = fast_softplus(r0.x + r0.y);
                    orow[k1] = fast_softplus(r1.x + r1.y);
                }
            }
        }
        __syncthreads();                     // final MV step done
        // drain: u = T_-1 = 2048 (buf 0)
        {
            const ulonglong2* hp2 = (const ulonglong2*)(h_s + (((T_ - 1) & 7) * H_));
            u64 s00 = 0ull, s01 = 0ull, s10 = 0ull, s11 = 0ull;
#pragma unroll
            for (int i = 0; i < 16; ++i) {
                ulonglong2 hv = hp2[i];
                s00 = ffma2_(hv.x, oe0[2 * i],     s00);
                s01 = ffma2_(hv.y, oe0[2 * i + 1], s01);
                s10 = ffma2_(hv.x, oe1[2 * i],     s10);
                s11 = ffma2_(hv.y, oe1[2 * i + 1], s11);
            }
            float2 r0 = unpack2(fadd2_(s00, s01));
            float2 r1 = unpack2(fadd2_(s10, s11));
            if (on) {
                float* orow = out_row + (size_t)(T_ - 1) * K_;
                orow[k0] = fast_softplus(r0.x + r0.y);
                orow[k1] = fast_softplus(r1.x + r1.y);
            }
        }
    }
}

extern "C" void kernel_launch(void* const* d_in, const int* in_sizes, int n_in,
                              void* d_out, int out_size) {
    const int*   ev   = (const int*)  d_in[0];
    const float* dt   = (const float*)d_in[1];
    const float* iemb = (const float*)d_in[2];
    const float* Wx   = (const float*)d_in[3];
    const float* Wh   = (const float*)d_in[4];
    const float* bias = (const float*)d_in[5];
    const float* oemb = (const float*)d_in[6];
    float* out = (float*)d_out;

    const size_t smem_bytes = (size_t)(2 * KE * MVT + 8 * H_ + 16) * sizeof(float);
    cudaFuncSetAttribute(scan_kernel, cudaFuncAttributeMaxDynamicSharedMemorySize,
                         (int)smem_bytes);

    build_pretab<<<KE, MVT>>>(iemb, Wx, bias);
    scan_kernel<<<B_, NTHR, smem_bytes>>>(ev, dt, Wh, oemb, out);
}